// round 2
// baseline (speedup 1.0000x reference)
#include <cuda_runtime.h>
#include <cuda_bf16.h>

#define N_NODES 50000
#define N_EDGES 800000
#define D 64          // D_IN == D_OUT == 64

// Scratch accumulator: rst = (1+eps)*feat, then scatter-added, then GEMM'd.
// __device__ global array = allocation-guard-legal scratch.
__device__ float g_rst[N_NODES * D];

// ---------------------------------------------------------------------------
// Kernel 1: rst = (1+eps) * feat   (vectorized float4)
// ---------------------------------------------------------------------------
__global__ __launch_bounds__(256) void init_kernel(
    const float4* __restrict__ feat, const float* __restrict__ eps,
    float4* __restrict__ rst)
{
    int i = blockIdx.x * blockDim.x + threadIdx.x;
    const int n = N_NODES * D / 4;
    if (i < n) {
        float s = 1.0f + eps[0];
        float4 f = feat[i];
        f.x *= s; f.y *= s; f.z *= s; f.w *= s;
        rst[i] = f;
    }
}

// ---------------------------------------------------------------------------
// Kernel 2: scatter-add  rst[dst] += feat[src]
// 16 threads per edge, one float4 (16B) each. Vectorized no-return reduction
// (red.global.add.v4.f32, sm_90+) quarters the atomic issue count.
// ---------------------------------------------------------------------------
__global__ __launch_bounds__(256) void scatter_kernel(
    const float4* __restrict__ feat,
    const int* __restrict__ src, const int* __restrict__ dst,
    float4* __restrict__ rst)
{
    int t = blockIdx.x * blockDim.x + threadIdx.x;
    int e = t >> 4;
    if (e >= N_EDGES) return;
    int c = t & 15;
    int s = __ldg(src + e);
    int d = __ldg(dst + e);
    float4 v = feat[(long)s * (D / 4) + c];
    float4* p = rst + (long)d * (D / 4) + c;
    asm volatile(
        "red.global.add.v4.f32 [%0], {%1, %2, %3, %4};"
        :: "l"(p), "f"(v.x), "f"(v.y), "f"(v.z), "f"(v.w)
        : "memory");
}

// ---------------------------------------------------------------------------
// Kernel 3: out = rst @ W^T + b
// W: [64,64] torch layout (out_feats, in_feats) -> out[r][j] = sum_k rst[r][k]*W[j][k]
// One thread per row; W + row tile staged in smem; acc[64] in registers;
// output restaged through smem for coalesced stores.
// ---------------------------------------------------------------------------
#define GROWS 96   // rows per block (96*17*16B tile + 16KB W < 48KB static smem)

__global__ __launch_bounds__(GROWS) void gemm_kernel(
    const float4* __restrict__ rst, const float4* __restrict__ W,
    const float* __restrict__ b, float4* __restrict__ out)
{
    __shared__ float4 Wsm[64 * 16];       // Wsm[j*16 + kq] = W[j][4kq..4kq+3]
    __shared__ float4 tile[GROWS * 17];   // padded row stride: 17 float4
    __shared__ float  bsm[64];

    const int tid  = threadIdx.x;
    const int row0 = blockIdx.x * GROWS;

    // Load W (16KB) cooperatively
    for (int i = tid; i < 64 * 16; i += GROWS) Wsm[i] = W[i];
    if (tid < 64) bsm[tid] = b[tid];

    // Load row tile coalesced
    for (int i = tid; i < GROWS * 16; i += GROWS) {
        int r = i >> 4, c = i & 15;
        int gr = row0 + r;
        float4 v = make_float4(0.f, 0.f, 0.f, 0.f);
        if (gr < N_NODES) v = rst[gr * 16 + c];
        tile[r * 17 + c] = v;
    }
    __syncthreads();

    float acc[64];
#pragma unroll
    for (int j = 0; j < 64; j++) acc[j] = 0.f;

    for (int kq = 0; kq < 16; kq++) {           // NOT unrolled (I$)
        float4 v = tile[tid * 17 + kq];
#pragma unroll
        for (int j = 0; j < 64; j++) {          // broadcast LDS.128 of W
            float4 w = Wsm[j * 16 + kq];
            acc[j] += v.x * w.x + v.y * w.y + v.z * w.z + v.w * w.w;
        }
    }

#pragma unroll
    for (int j = 0; j < 64; j++) acc[j] += bsm[j];

    // Restage through smem for coalesced global stores
    __syncthreads();
#pragma unroll
    for (int q = 0; q < 16; q++)
        tile[tid * 17 + q] =
            make_float4(acc[4 * q], acc[4 * q + 1], acc[4 * q + 2], acc[4 * q + 3]);
    __syncthreads();

    for (int i = tid; i < GROWS * 16; i += GROWS) {
        int r = i >> 4, c = i & 15;
        int gr = row0 + r;
        if (gr < N_NODES) out[gr * 16 + c] = tile[r * 17 + c];
    }
}

// ---------------------------------------------------------------------------
// Launch: inputs per metadata order: feat, W, b, eps, src, dst
// ---------------------------------------------------------------------------
extern "C" void kernel_launch(void* const* d_in, const int* in_sizes, int n_in,
                              void* d_out, int out_size)
{
    const float4* feat = (const float4*)d_in[0];
    const float4* W    = (const float4*)d_in[1];
    const float*  b    = (const float*)d_in[2];
    const float*  eps  = (const float*)d_in[3];
    const int*    src  = (const int*)d_in[4];
    const int*    dst  = (const int*)d_in[5];
    float4*       out  = (float4*)d_out;

    float4* rst4;
    cudaGetSymbolAddress((void**)&rst4, g_rst);

    // 1) rst = (1+eps)*feat
    {
        int n = N_NODES * D / 4;
        init_kernel<<<(n + 255) / 256, 256>>>(feat, eps, rst4);
    }
    // 2) rst[dst] += feat[src]
    {
        long total = (long)N_EDGES * 16;
        int blocks = (int)((total + 255) / 256);
        scatter_kernel<<<blocks, 256>>>(feat, src, dst, rst4);
    }
    // 3) out = rst @ W^T + b
    {
        int blocks = (N_NODES + GROWS - 1) / GROWS;
        gemm_kernel<<<blocks, GROWS>>>((const float4*)rst4, W, b, out);
    }
}